// round 4
// baseline (speedup 1.0000x reference)
#include <cuda_runtime.h>
#include <cstdint>

// Problem constants (fixed shapes for InferenceNet_10118942949387)
#define BDIM 8
#define TDIM 8192
#define MROWS (BDIM * TDIM)   // 65536 rows
#define IDIM 256
#define HDIM 1024
#define ODIM 256
#define CDIM 128
#define OUT_ELEMS ((size_t)MROWS * ODIM)   // 16,777,216

// Device scratch:
//  g_h : dense hidden activation (encoder -> topk)
//  g_sp: per-row compacted (val, idx) pairs of the 256 surviving units
__device__ float g_h[(size_t)MROWS * HDIM];
__device__ uint2 g_sp[(size_t)MROWS * 2 * CDIM];

// ===========================================================================
// Encoder SGEMM (validated in round 2 — numerics are load-bearing for the
// exact top-k ranks; do not change accumulation order).
// 128x128 tile, 256 threads, 8x8/thread split 4+4, double-buffered smem.
// ===========================================================================
__global__ __launch_bounds__(256) void enc_kernel(
    const float* __restrict__ A, const float* __restrict__ W,
    const float* __restrict__ bias, float* __restrict__ C) {
  __shared__ float As[2][8][132];
  __shared__ float Bs[2][8][132];
  const int tid = threadIdx.x;
  const int tx = tid & 15;
  const int ty = tid >> 4;
  const int row0 = blockIdx.y * 128;
  const int col0 = blockIdx.x * 128;

  const int lm = tid >> 1;
  const int lk = (tid & 1) * 4;
  const int lkc = tid >> 5;
  const int lc = (tid & 31) * 4;

  const float* aptr = A + (size_t)(row0 + lm) * IDIM + lk;
  const float* bptr = W + (size_t)lkc * HDIM + col0 + lc;

  float acc[8][8];
#pragma unroll
  for (int i = 0; i < 8; i++)
#pragma unroll
    for (int j = 0; j < 8; j++) acc[i][j] = 0.f;

  float4 av = *(const float4*)aptr;
  float4 bv = *(const float4*)bptr;
  As[0][lk + 0][lm] = av.x;
  As[0][lk + 1][lm] = av.y;
  As[0][lk + 2][lm] = av.z;
  As[0][lk + 3][lm] = av.w;
  *(float4*)&Bs[0][lkc][lc] = bv;
  __syncthreads();

  int buf = 0;
  for (int k0 = 0; k0 < IDIM; k0 += 8) {
    const bool more = (k0 + 8 < IDIM);
    if (more) {
      av = *(const float4*)(aptr + k0 + 8);
      bv = *(const float4*)(bptr + (size_t)(k0 + 8) * HDIM);
    }
#pragma unroll
    for (int kc = 0; kc < 8; kc++) {
      float4 a0 = *(const float4*)&As[buf][kc][ty * 4];
      float4 a1 = *(const float4*)&As[buf][kc][64 + ty * 4];
      float4 bq0 = *(const float4*)&Bs[buf][kc][tx * 4];
      float4 bq1 = *(const float4*)&Bs[buf][kc][64 + tx * 4];
      float a[8] = {a0.x, a0.y, a0.z, a0.w, a1.x, a1.y, a1.z, a1.w};
      float b[8] = {bq0.x, bq0.y, bq0.z, bq0.w, bq1.x, bq1.y, bq1.z, bq1.w};
#pragma unroll
      for (int i = 0; i < 8; i++)
#pragma unroll
        for (int j = 0; j < 8; j++) acc[i][j] = fmaf(a[i], b[j], acc[i][j]);
    }
    if (more) {
      buf ^= 1;
      As[buf][lk + 0][lm] = av.x;
      As[buf][lk + 1][lm] = av.y;
      As[buf][lk + 2][lm] = av.z;
      As[buf][lk + 3][lm] = av.w;
      *(float4*)&Bs[buf][lkc][lc] = bv;
      __syncthreads();
    }
  }

#pragma unroll
  for (int i = 0; i < 8; i++) {
    const int r = row0 + ((i < 4) ? (ty * 4 + i) : (64 + ty * 4 + (i - 4)));
    const int c0 = col0 + tx * 4;
    const int c1 = col0 + 64 + tx * 4;
    float4 o0, o1;
    o0.x = acc[i][0] + bias[c0 + 0];
    o0.y = acc[i][1] + bias[c0 + 1];
    o0.z = acc[i][2] + bias[c0 + 2];
    o0.w = acc[i][3] + bias[c0 + 3];
    o1.x = acc[i][4] + bias[c1 + 0];
    o1.y = acc[i][5] + bias[c1 + 1];
    o1.z = acc[i][6] + bias[c1 + 2];
    o1.w = acc[i][7] + bias[c1 + 3];
    *(float4*)(C + (size_t)r * HDIM + c0) = o0;
    *(float4*)(C + (size_t)r * HDIM + c1) = o1;
  }
}

// ===========================================================================
// Top-k: warp-per-row, register-resident. Selection logic identical to the
// validated round-2 version (exact jax.lax.top_k tie semantics via u64 keys).
// Additionally compacts the 256 surviving (val, idx) pairs into g_sp via
// ballot-prefix (order within the list is irrelevant for the sparse decoder).
// ===========================================================================
#define TK_WARPS 8
#define TK_BINS 1024
#define TK_CAP 320

__global__ __launch_bounds__(256) void topk_kernel(
    const float* __restrict__ mprev, float* __restrict__ mask_out) {
  __shared__ unsigned int sh_hist[TK_WARPS][TK_BINS];
  __shared__ unsigned long long sh_cand[TK_WARPS][TK_CAP];
  __shared__ unsigned int sh_ctr[TK_WARPS][2];
  __shared__ unsigned long long sh_key[TK_WARPS][2];

  const int lane = threadIdx.x & 31;
  const int w = threadIdx.x >> 5;
  const size_t row = (size_t)blockIdx.x * TK_WARPS + w;
  const float* hrow = g_h + row * HDIM;
  const float* mrow = mprev + row * HDIM;

  unsigned int* hst = sh_hist[w];
#pragma unroll
  for (int j = 0; j < TK_BINS / 32; j++) hst[j * 32 + lane] = 0;
  if (lane < 2) sh_ctr[w][lane] = 0;
  __syncwarp();

  // Single load of the row into registers.
  float v[32], mp[32];
  unsigned int u[32];
  unsigned int maxbin = 0;
#pragma unroll
  for (int j = 0; j < 8; j++) {
    float4 hv = ((const float4*)hrow)[j * 32 + lane];
    float4 mv = ((const float4*)mrow)[j * 32 + lane];
    float vv[4] = {hv.x, hv.y, hv.z, hv.w};
    float mm[4] = {mv.x, mv.y, mv.z, mv.w};
#pragma unroll
    for (int i = 0; i < 4; i++) {
      float t = (mm[i] > 0.f) ? 0.f : vv[i];
      v[j * 4 + i] = t;
      mp[j * 4 + i] = mm[i];
      unsigned int uu = __float_as_uint(t * t);
      u[j * 4 + i] = uu;
      unsigned int b = uu >> 21;
      atomicAdd(&hst[b], 1u);
      maxbin = max(maxbin, b);
    }
  }
#pragma unroll
  for (int o = 16; o > 0; o >>= 1)
    maxbin = max(maxbin, __shfl_xor_sync(0xffffffffu, maxbin, o));
  __syncwarp();

  // Suffix scan (descending bins) fused with boundary detection.
  unsigned int bin0 = 0, rem0 = 0, bin1 = 0, rem1 = 0;
  bool f0 = false, f1 = false;
  unsigned int carry = 0;
  const int jstart = (int)(TK_BINS - 1 - maxbin) >> 5;
  for (int j = jstart; j < TK_BINS / 32; j++) {
    const int b = TK_BINS - 1 - (j * 32 + lane);
    const unsigned int cnt = hst[b];
    unsigned int s = cnt;
#pragma unroll
    for (int o = 1; o < 32; o <<= 1) {
      unsigned int n = __shfl_up_sync(0xffffffffu, s, o);
      if (lane >= o) s += n;
    }
    const unsigned int S = carry + s;
    const unsigned int Sp = S - cnt;
    if (cnt && S >= CDIM && Sp < CDIM)         { bin0 = b; rem0 = CDIM - Sp; f0 = true; }
    if (cnt && S >= 2 * CDIM && Sp < 2 * CDIM) { bin1 = b; rem1 = 2 * CDIM - Sp; f1 = true; }
    carry += __shfl_sync(0xffffffffu, s, 31);
    if (carry >= 2 * CDIM) break;
  }
  {
    unsigned int m0 = __ballot_sync(0xffffffffu, f0);
    int src = __ffs(m0) - 1;
    bin0 = __shfl_sync(0xffffffffu, bin0, src);
    rem0 = __shfl_sync(0xffffffffu, rem0, src);
    unsigned int m1 = __ballot_sync(0xffffffffu, f1);
    src = __ffs(m1) - 1;
    bin1 = __shfl_sync(0xffffffffu, bin1, src);
    rem1 = __shfl_sync(0xffffffffu, rem1, src);
  }
  const bool same_bin = (bin0 == bin1);

  // Gather boundary candidates from registers.
#pragma unroll
  for (int e = 0; e < 32; e++) {
    const unsigned int b = u[e] >> 21;
    const int idx = (((e >> 2) * 32 + lane) << 2) + (e & 3);
    const unsigned long long key =
        ((unsigned long long)u[e] << 10) | (unsigned long long)(1023 - idx);
    if (b == bin0) {
      unsigned int p = atomicAdd(&sh_ctr[w][0], 1u);
      if (p < TK_CAP) sh_cand[w][p] = key;
    } else if (!same_bin && b == bin1) {
      unsigned int p = atomicAdd(&sh_ctr[w][1], 1u);
      if (p < TK_CAP) sh_cand[w][TK_CAP - 1 - p] = key;
    }
  }
  __syncwarp();
  const unsigned int n0 = sh_ctr[w][0];
  const unsigned int n1 = sh_ctr[w][1];

  for (unsigned int c = lane; c < n0; c += 32) {
    const unsigned long long kc_ = sh_cand[w][c];
    unsigned int r = 0;
    for (unsigned int q = 0; q < n0; q++) r += (sh_cand[w][q] > kc_) ? 1u : 0u;
    if (r == rem0 - 1u) sh_key[w][0] = kc_;
    if (same_bin && r == rem1 - 1u) sh_key[w][1] = kc_;
  }
  if (!same_bin) {
    for (unsigned int c = lane; c < n1; c += 32) {
      const unsigned long long kc_ = sh_cand[w][TK_CAP - 1 - c];
      unsigned int r = 0;
      for (unsigned int q = 0; q < n1; q++)
        r += (sh_cand[w][TK_CAP - 1 - q] > kc_) ? 1u : 0u;
      if (r == rem1 - 1u) sh_key[w][1] = kc_;
    }
  }
  __syncwarp();
  const unsigned long long k128 = sh_key[w][0];
  const unsigned long long k256 = sh_key[w][1];

  // Write mask_new + ballot-compact the 256 surviving (val, idx) pairs.
  uint2* sp = g_sp + row * (2 * CDIM);
  unsigned int base = 0;
#pragma unroll
  for (int j = 0; j < 8; j++) {
    float4 mo;
    float* mq = (float*)&mo;
#pragma unroll
    for (int i = 0; i < 4; i++) {
      const int e = j * 4 + i;
      const int idx = (j * 32 + lane) * 4 + i;
      const unsigned long long key =
          ((unsigned long long)u[e] << 10) | (unsigned long long)(1023 - idx);
      mq[i] = mp[e] + ((key >= k128) ? 1.f : 0.f);
      const bool keep = (key >= k256);
      const unsigned int bal = __ballot_sync(0xffffffffu, keep);
      if (keep) {
        const unsigned int pos =
            base + __popc(bal & ((1u << lane) - 1u));
        sp[pos] = make_uint2(__float_as_uint(v[e]), (unsigned int)idx);
      }
      base += __popc(bal);
    }
    ((float4*)(mask_out + row * HDIM))[j * 32 + lane] = mo;
  }
}

// ===========================================================================
// Sparse decoder: out[r, :] = sum over the 256 surviving (val, idx) pairs of
// val * W[idx, :] + bias.  fp32 exact (zero terms skipped; order-only change
// vs dense, and `out` has ample error budget anyway).
// Warp per row, 8 warps/CTA. W (1 MB) is L2-resident: each entry does
// 2x LDG.128 per lane + 8 FFMA. Entries staged in smem, broadcast via LDS.
// ===========================================================================
#define DEC_WARPS 8
__global__ __launch_bounds__(256) void dec_sparse_kernel(
    const float* __restrict__ Wself, const float* __restrict__ bself,
    const float* __restrict__ Wsrc,  const float* __restrict__ bsrc,
    const int* __restrict__ sel, float* __restrict__ out) {
  __shared__ uint2 ent[DEC_WARPS][2 * CDIM];

  const float* __restrict__ W;
  const float* __restrict__ bias;
  if (*sel != 0) { W = Wsrc; bias = bsrc; }
  else           { W = Wself; bias = bself; }

  const int lane = threadIdx.x & 31;
  const int w = threadIdx.x >> 5;
  const size_t row = (size_t)blockIdx.x * DEC_WARPS + w;

  // Stage this row's 256 entries into smem.
  const uint2* src = g_sp + row * (2 * CDIM);
#pragma unroll
  for (int j = 0; j < 8; j++) ent[w][j * 32 + lane] = src[j * 32 + lane];
  __syncwarp();

  float4 acc0 = make_float4(0.f, 0.f, 0.f, 0.f);
  float4 acc1 = make_float4(0.f, 0.f, 0.f, 0.f);

#pragma unroll 4
  for (int e = 0; e < 2 * CDIM; e++) {
    const uint2 p = ent[w][e];                  // broadcast LDS
    const float val = __uint_as_float(p.x);
    const float4* wr = (const float4*)(W + (size_t)p.y * ODIM);
    const float4 w0 = wr[lane];                 // cols lane*4 .. +3
    const float4 w1 = wr[32 + lane];            // cols 128+lane*4 .. +3
    acc0.x = fmaf(val, w0.x, acc0.x);
    acc0.y = fmaf(val, w0.y, acc0.y);
    acc0.z = fmaf(val, w0.z, acc0.z);
    acc0.w = fmaf(val, w0.w, acc0.w);
    acc1.x = fmaf(val, w1.x, acc1.x);
    acc1.y = fmaf(val, w1.y, acc1.y);
    acc1.z = fmaf(val, w1.z, acc1.z);
    acc1.w = fmaf(val, w1.w, acc1.w);
  }

  const float4 b0 = ((const float4*)bias)[lane];
  const float4 b1 = ((const float4*)bias)[32 + lane];
  acc0.x += b0.x; acc0.y += b0.y; acc0.z += b0.z; acc0.w += b0.w;
  acc1.x += b1.x; acc1.y += b1.y; acc1.z += b1.z; acc1.w += b1.w;
  float* orow = out + row * ODIM;
  ((float4*)orow)[lane] = acc0;
  ((float4*)orow)[32 + lane] = acc1;
}

// ===========================================================================
// Inputs: x, mask_prev, W_enc, b_enc, W_dec_self, b_dec_self, W_dec_src,
// b_dec_src, decoder_type. Output: [out | mask_new].
// ===========================================================================
extern "C" void kernel_launch(void* const* d_in, const int* in_sizes, int n_in,
                              void* d_out, int out_size) {
  const float* x          = (const float*)d_in[0];
  const float* mask_prev  = (const float*)d_in[1];
  const float* W_enc      = (const float*)d_in[2];
  const float* b_enc      = (const float*)d_in[3];
  const float* W_dec_self = (const float*)d_in[4];
  const float* b_dec_self = (const float*)d_in[5];
  const float* W_dec_src  = (const float*)d_in[6];
  const float* b_dec_src  = (const float*)d_in[7];
  const int*   dtype      = (const int*)d_in[8];

  float* out      = (float*)d_out;
  float* mask_out = out + OUT_ELEMS;
  float* h        = nullptr;
  cudaGetSymbolAddress((void**)&h, g_h);

  dim3 g1(HDIM / 128, MROWS / 128);   // (8, 512)
  enc_kernel<<<g1, 256>>>(x, W_enc, b_enc, h);

  topk_kernel<<<MROWS / TK_WARPS, 256>>>(mask_prev, mask_out);

  dec_sparse_kernel<<<MROWS / DEC_WARPS, 256>>>(
      W_dec_self, b_dec_self, W_dec_src, b_dec_src, dtype, out);
}

// round 5
// speedup vs baseline: 1.0293x; 1.0293x over previous
#include <cuda_runtime.h>
#include <cstdint>

// Problem constants (fixed shapes for InferenceNet_10118942949387)
#define BDIM 8
#define TDIM 8192
#define MROWS (BDIM * TDIM)   // 65536 rows
#define IDIM 256
#define HDIM 1024
#define ODIM 256
#define CDIM 128
#define OUT_ELEMS ((size_t)MROWS * ODIM)   // 16,777,216

// Dense hidden activation scratch (encoder -> topk -> decoder).
__device__ float g_h[(size_t)MROWS * HDIM];

// Packed f32x2 helpers (Blackwell base ISA, sm_100+; NOT an 'a'-gated feature).
// fma.rn.f32x2 = two independent IEEE fp32 FMAs -> bit-identical to 2x fmaf.
__device__ __forceinline__ void fma_f32x2(unsigned long long& d,
                                          unsigned long long a,
                                          unsigned long long b) {
  asm("fma.rn.f32x2 %0, %1, %2, %0;" : "+l"(d) : "l"(a), "l"(b));
}
__device__ __forceinline__ unsigned long long pack_dup(float x) {
  unsigned long long r;
  asm("mov.b64 %0, {%1, %1};" : "=l"(r) : "f"(x));
  return r;
}
__device__ __forceinline__ float2 unpack2(unsigned long long p) {
  float lo, hi;
  asm("mov.b64 {%0, %1}, %2;" : "=f"(lo), "=f"(hi) : "l"(p));
  return make_float2(lo, hi);
}

// ===========================================================================
// SGEMM (f32x2 packed): C[r,c] = sum_k A[r,k]*W[k,c] + bias[c]
// 128x128 tile, 256 threads, 8x8/thread split 4+4, double-buffered smem.
// Accumulation per output element is a sequential chained FMA over ascending
// k — bit-identical to the validated round-2 kernel (top-k rank safety).
// ===========================================================================
template <int KD, int ND>
__global__ __launch_bounds__(256) void gemm_kernel(
    const float* __restrict__ A,
    const float* __restrict__ W0, const float* __restrict__ b0,
    const float* __restrict__ W1, const float* __restrict__ b1,
    const int* __restrict__ sel, float* __restrict__ C) {
  __shared__ __align__(16) float As[2][8][132];
  __shared__ __align__(16) float Bs[2][8][132];

  const float* __restrict__ W;
  const float* __restrict__ bias;
  if (sel != nullptr && *sel != 0) { W = W1; bias = b1; }
  else                             { W = W0; bias = b0; }

  const int tid = threadIdx.x;
  const int tx = tid & 15;
  const int ty = tid >> 4;
  const int row0 = blockIdx.y * 128;
  const int col0 = blockIdx.x * 128;

  const int lm  = tid >> 1;
  const int lk  = (tid & 1) * 4;
  const int lkc = tid >> 5;
  const int lc  = (tid & 31) * 4;

  const float* aptr = A + (size_t)(row0 + lm) * KD + lk;
  const float* bptr = W + (size_t)lkc * ND + col0 + lc;

  // acc2[i][j] holds columns (2j, 2j+1) of the 8-wide per-thread column strip.
  unsigned long long acc2[8][4];
#pragma unroll
  for (int i = 0; i < 8; i++)
#pragma unroll
    for (int j = 0; j < 4; j++) acc2[i][j] = 0ull;

  float4 av = *(const float4*)aptr;
  float4 bv = *(const float4*)bptr;
  As[0][lk + 0][lm] = av.x;
  As[0][lk + 1][lm] = av.y;
  As[0][lk + 2][lm] = av.z;
  As[0][lk + 3][lm] = av.w;
  *(float4*)&Bs[0][lkc][lc] = bv;
  __syncthreads();

  int buf = 0;
  for (int k0 = 0; k0 < KD; k0 += 8) {
    const bool more = (k0 + 8 < KD);
    if (more) {
      av = *(const float4*)(aptr + k0 + 8);
      bv = *(const float4*)(bptr + (size_t)(k0 + 8) * ND);
    }
#pragma unroll
    for (int kc = 0; kc < 8; kc++) {
      float4 a0 = *(const float4*)&As[buf][kc][ty * 4];
      float4 a1 = *(const float4*)&As[buf][kc][64 + ty * 4];
      const ulonglong2 bp0 = *(const ulonglong2*)&Bs[buf][kc][tx * 4];
      const ulonglong2 bp1 = *(const ulonglong2*)&Bs[buf][kc][64 + tx * 4];
      const unsigned long long bb[4] = {bp0.x, bp0.y, bp1.x, bp1.y};
      const float a[8] = {a0.x, a0.y, a0.z, a0.w, a1.x, a1.y, a1.z, a1.w};
#pragma unroll
      for (int i = 0; i < 8; i++) {
        const unsigned long long ap = pack_dup(a[i]);
#pragma unroll
        for (int j = 0; j < 4; j++) fma_f32x2(acc2[i][j], ap, bb[j]);
      }
    }
    if (more) {
      buf ^= 1;
      As[buf][lk + 0][lm] = av.x;
      As[buf][lk + 1][lm] = av.y;
      As[buf][lk + 2][lm] = av.z;
      As[buf][lk + 3][lm] = av.w;
      *(float4*)&Bs[buf][lkc][lc] = bv;
      __syncthreads();
    }
  }

#pragma unroll
  for (int i = 0; i < 8; i++) {
    const int r = row0 + ((i < 4) ? (ty * 4 + i) : (64 + ty * 4 + (i - 4)));
    const int c0 = col0 + tx * 4;
    const int c1 = col0 + 64 + tx * 4;
    const float2 p0 = unpack2(acc2[i][0]);
    const float2 p1 = unpack2(acc2[i][1]);
    const float2 p2 = unpack2(acc2[i][2]);
    const float2 p3 = unpack2(acc2[i][3]);
    float4 o0, o1;
    o0.x = p0.x + bias[c0 + 0];
    o0.y = p0.y + bias[c0 + 1];
    o0.z = p1.x + bias[c0 + 2];
    o0.w = p1.y + bias[c0 + 3];
    o1.x = p2.x + bias[c1 + 0];
    o1.y = p2.y + bias[c1 + 1];
    o1.z = p3.x + bias[c1 + 2];
    o1.w = p3.y + bias[c1 + 3];
    *(float4*)(C + (size_t)r * ND + c0) = o0;
    *(float4*)(C + (size_t)r * ND + c1) = o1;
  }
}

// ===========================================================================
// Top-k: warp-per-row, register-resident, single data pass. Selection logic
// identical to the validated round-2/3 version (exact jax.lax.top_k tie
// semantics via distinct u64 keys). Writes masked h (top-256 kept) back to
// g_h and mask_new (mprev + top-128 indicator) to the output.
// ===========================================================================
#define TK_WARPS 8
#define TK_BINS 1024
#define TK_CAP 320

__global__ __launch_bounds__(256) void topk_kernel(
    const float* __restrict__ mprev, float* __restrict__ mask_out) {
  __shared__ unsigned int sh_hist[TK_WARPS][TK_BINS];
  __shared__ unsigned long long sh_cand[TK_WARPS][TK_CAP];
  __shared__ unsigned int sh_ctr[TK_WARPS][2];
  __shared__ unsigned long long sh_key[TK_WARPS][2];

  const int lane = threadIdx.x & 31;
  const int w = threadIdx.x >> 5;
  const size_t row = (size_t)blockIdx.x * TK_WARPS + w;
  float* hrow = g_h + row * HDIM;
  const float* mrow = mprev + row * HDIM;

  unsigned int* hst = sh_hist[w];
#pragma unroll
  for (int j = 0; j < TK_BINS / 32; j++) hst[j * 32 + lane] = 0;
  if (lane < 2) sh_ctr[w][lane] = 0;
  __syncwarp();

  // Single load of the row into registers.
  float v[32], mp[32];
  unsigned int u[32];
  unsigned int maxbin = 0;
#pragma unroll
  for (int j = 0; j < 8; j++) {
    float4 hv = ((const float4*)hrow)[j * 32 + lane];
    float4 mv = ((const float4*)mrow)[j * 32 + lane];
    float vv[4] = {hv.x, hv.y, hv.z, hv.w};
    float mm[4] = {mv.x, mv.y, mv.z, mv.w};
#pragma unroll
    for (int i = 0; i < 4; i++) {
      float t = (mm[i] > 0.f) ? 0.f : vv[i];
      v[j * 4 + i] = t;
      mp[j * 4 + i] = mm[i];
      unsigned int uu = __float_as_uint(t * t);
      u[j * 4 + i] = uu;
      unsigned int b = uu >> 21;
      atomicAdd(&hst[b], 1u);
      maxbin = max(maxbin, b);
    }
  }
#pragma unroll
  for (int o = 16; o > 0; o >>= 1)
    maxbin = max(maxbin, __shfl_xor_sync(0xffffffffu, maxbin, o));
  __syncwarp();

  // Suffix scan (descending bins) fused with boundary detection.
  unsigned int bin0 = 0, rem0 = 0, bin1 = 0, rem1 = 0;
  bool f0 = false, f1 = false;
  unsigned int carry = 0;
  const int jstart = (int)(TK_BINS - 1 - maxbin) >> 5;
  for (int j = jstart; j < TK_BINS / 32; j++) {
    const int b = TK_BINS - 1 - (j * 32 + lane);
    const unsigned int cnt = hst[b];
    unsigned int s = cnt;
#pragma unroll
    for (int o = 1; o < 32; o <<= 1) {
      unsigned int n = __shfl_up_sync(0xffffffffu, s, o);
      if (lane >= o) s += n;
    }
    const unsigned int S = carry + s;
    const unsigned int Sp = S - cnt;
    if (cnt && S >= CDIM && Sp < CDIM)         { bin0 = b; rem0 = CDIM - Sp; f0 = true; }
    if (cnt && S >= 2 * CDIM && Sp < 2 * CDIM) { bin1 = b; rem1 = 2 * CDIM - Sp; f1 = true; }
    carry += __shfl_sync(0xffffffffu, s, 31);
    if (carry >= 2 * CDIM) break;
  }
  {
    unsigned int m0 = __ballot_sync(0xffffffffu, f0);
    int src = __ffs(m0) - 1;
    bin0 = __shfl_sync(0xffffffffu, bin0, src);
    rem0 = __shfl_sync(0xffffffffu, rem0, src);
    unsigned int m1 = __ballot_sync(0xffffffffu, f1);
    src = __ffs(m1) - 1;
    bin1 = __shfl_sync(0xffffffffu, bin1, src);
    rem1 = __shfl_sync(0xffffffffu, rem1, src);
  }
  const bool same_bin = (bin0 == bin1);

  // Gather boundary candidates from registers.
#pragma unroll
  for (int e = 0; e < 32; e++) {
    const unsigned int b = u[e] >> 21;
    const int idx = (((e >> 2) * 32 + lane) << 2) + (e & 3);
    const unsigned long long key =
        ((unsigned long long)u[e] << 10) | (unsigned long long)(1023 - idx);
    if (b == bin0) {
      unsigned int p = atomicAdd(&sh_ctr[w][0], 1u);
      if (p < TK_CAP) sh_cand[w][p] = key;
    } else if (!same_bin && b == bin1) {
      unsigned int p = atomicAdd(&sh_ctr[w][1], 1u);
      if (p < TK_CAP) sh_cand[w][TK_CAP - 1 - p] = key;
    }
  }
  __syncwarp();
  const unsigned int n0 = sh_ctr[w][0];
  const unsigned int n1 = sh_ctr[w][1];

  for (unsigned int c = lane; c < n0; c += 32) {
    const unsigned long long kc_ = sh_cand[w][c];
    unsigned int r = 0;
    for (unsigned int q = 0; q < n0; q++) r += (sh_cand[w][q] > kc_) ? 1u : 0u;
    if (r == rem0 - 1u) sh_key[w][0] = kc_;
    if (same_bin && r == rem1 - 1u) sh_key[w][1] = kc_;
  }
  if (!same_bin) {
    for (unsigned int c = lane; c < n1; c += 32) {
      const unsigned long long kc_ = sh_cand[w][TK_CAP - 1 - c];
      unsigned int r = 0;
      for (unsigned int q = 0; q < n1; q++)
        r += (sh_cand[w][TK_CAP - 1 - q] > kc_) ? 1u : 0u;
      if (r == rem1 - 1u) sh_key[w][1] = kc_;
    }
  }
  __syncwarp();
  const unsigned long long k128 = sh_key[w][0];
  const unsigned long long k256 = sh_key[w][1];

  // Write masked h and mask_new from registers.
#pragma unroll
  for (int j = 0; j < 8; j++) {
    float4 ho, mo;
    float* hp = (float*)&ho;
    float* mq = (float*)&mo;
#pragma unroll
    for (int i = 0; i < 4; i++) {
      const int e = j * 4 + i;
      const int idx = (j * 32 + lane) * 4 + i;
      const unsigned long long key =
          ((unsigned long long)u[e] << 10) | (unsigned long long)(1023 - idx);
      hp[i] = (key >= k256) ? v[e] : 0.f;
      mq[i] = mp[e] + ((key >= k128) ? 1.f : 0.f);
    }
    ((float4*)hrow)[j * 32 + lane] = ho;
    ((float4*)(mask_out + row * HDIM))[j * 32 + lane] = mo;
  }
}

// ===========================================================================
// Inputs: x, mask_prev, W_enc, b_enc, W_dec_self, b_dec_self, W_dec_src,
// b_dec_src, decoder_type. Output: [out | mask_new].
// ===========================================================================
extern "C" void kernel_launch(void* const* d_in, const int* in_sizes, int n_in,
                              void* d_out, int out_size) {
  const float* x          = (const float*)d_in[0];
  const float* mask_prev  = (const float*)d_in[1];
  const float* W_enc      = (const float*)d_in[2];
  const float* b_enc      = (const float*)d_in[3];
  const float* W_dec_self = (const float*)d_in[4];
  const float* b_dec_self = (const float*)d_in[5];
  const float* W_dec_src  = (const float*)d_in[6];
  const float* b_dec_src  = (const float*)d_in[7];
  const int*   dtype      = (const int*)d_in[8];

  float* out      = (float*)d_out;
  float* mask_out = out + OUT_ELEMS;
  float* h        = nullptr;
  cudaGetSymbolAddress((void**)&h, g_h);

  dim3 g1(HDIM / 128, MROWS / 128);   // (8, 512)
  gemm_kernel<IDIM, HDIM><<<g1, 256>>>(x, W_enc, b_enc, W_enc, b_enc,
                                       nullptr, h);

  topk_kernel<<<MROWS / TK_WARPS, 256>>>(mask_prev, mask_out);

  dim3 g3(ODIM / 128, MROWS / 128);   // (2, 512)
  gemm_kernel<HDIM, ODIM><<<g3, 256>>>(h, W_dec_self, b_dec_self,
                                       W_dec_src, b_dec_src, dtype, out);
}

// round 6
// speedup vs baseline: 1.2413x; 1.2060x over previous
#include <cuda_runtime.h>
#include <cstdint>

// Problem constants (fixed shapes for InferenceNet_10118942949387)
#define BDIM 8
#define TDIM 8192
#define MROWS (BDIM * TDIM)   // 65536 rows
#define IDIM 256
#define HDIM 1024
#define ODIM 256
#define CDIM 128
#define OUT_ELEMS ((size_t)MROWS * ODIM)   // 16,777,216

// Dense hidden activation scratch (encoder -> topk -> decoder).
__device__ float g_h[(size_t)MROWS * HDIM];

// Packed f32x2 helpers (Blackwell base ISA; bit-identical to 2x fmaf).
__device__ __forceinline__ void fma_f32x2(unsigned long long& d,
                                          unsigned long long a,
                                          unsigned long long b) {
  asm("fma.rn.f32x2 %0, %1, %2, %0;" : "+l"(d) : "l"(a), "l"(b));
}
__device__ __forceinline__ unsigned long long pack_dup(float x) {
  unsigned long long r;
  asm("mov.b64 %0, {%1, %1};" : "=l"(r) : "f"(x));
  return r;
}
__device__ __forceinline__ float2 unpack2(unsigned long long p) {
  float lo, hi;
  asm("mov.b64 {%0, %1}, %2;" : "=f"(lo), "=f"(hi) : "l"(p));
  return make_float2(lo, hi);
}
__device__ __forceinline__ uint32_t cvt_tf32(float f) {
  uint32_t u;
  asm("cvt.rna.tf32.f32 %0, %1;" : "=r"(u) : "f"(f));
  return u;
}

// ===========================================================================
// Encoder SGEMM (f32x2 packed) — UNCHANGED from round 5 (validated numerics:
// sequential chained FMA over ascending k; top-k ranks depend on this).
// ===========================================================================
__global__ __launch_bounds__(256) void enc_kernel(
    const float* __restrict__ A, const float* __restrict__ W,
    const float* __restrict__ bias, float* __restrict__ C) {
  __shared__ __align__(16) float As[2][8][132];
  __shared__ __align__(16) float Bs[2][8][132];

  const int tid = threadIdx.x;
  const int tx = tid & 15;
  const int ty = tid >> 4;
  const int row0 = blockIdx.y * 128;
  const int col0 = blockIdx.x * 128;

  const int lm  = tid >> 1;
  const int lk  = (tid & 1) * 4;
  const int lkc = tid >> 5;
  const int lc  = (tid & 31) * 4;

  const float* aptr = A + (size_t)(row0 + lm) * IDIM + lk;
  const float* bptr = W + (size_t)lkc * HDIM + col0 + lc;

  unsigned long long acc2[8][4];
#pragma unroll
  for (int i = 0; i < 8; i++)
#pragma unroll
    for (int j = 0; j < 4; j++) acc2[i][j] = 0ull;

  float4 av = *(const float4*)aptr;
  float4 bv = *(const float4*)bptr;
  As[0][lk + 0][lm] = av.x;
  As[0][lk + 1][lm] = av.y;
  As[0][lk + 2][lm] = av.z;
  As[0][lk + 3][lm] = av.w;
  *(float4*)&Bs[0][lkc][lc] = bv;
  __syncthreads();

  int buf = 0;
  for (int k0 = 0; k0 < IDIM; k0 += 8) {
    const bool more = (k0 + 8 < IDIM);
    if (more) {
      av = *(const float4*)(aptr + k0 + 8);
      bv = *(const float4*)(bptr + (size_t)(k0 + 8) * HDIM);
    }
#pragma unroll
    for (int kc = 0; kc < 8; kc++) {
      float4 a0 = *(const float4*)&As[buf][kc][ty * 4];
      float4 a1 = *(const float4*)&As[buf][kc][64 + ty * 4];
      const ulonglong2 bp0 = *(const ulonglong2*)&Bs[buf][kc][tx * 4];
      const ulonglong2 bp1 = *(const ulonglong2*)&Bs[buf][kc][64 + tx * 4];
      const unsigned long long bb[4] = {bp0.x, bp0.y, bp1.x, bp1.y};
      const float a[8] = {a0.x, a0.y, a0.z, a0.w, a1.x, a1.y, a1.z, a1.w};
#pragma unroll
      for (int i = 0; i < 8; i++) {
        const unsigned long long ap = pack_dup(a[i]);
#pragma unroll
        for (int j = 0; j < 4; j++) fma_f32x2(acc2[i][j], ap, bb[j]);
      }
    }
    if (more) {
      buf ^= 1;
      As[buf][lk + 0][lm] = av.x;
      As[buf][lk + 1][lm] = av.y;
      As[buf][lk + 2][lm] = av.z;
      As[buf][lk + 3][lm] = av.w;
      *(float4*)&Bs[buf][lkc][lc] = bv;
      __syncthreads();
    }
  }

#pragma unroll
  for (int i = 0; i < 8; i++) {
    const int r = row0 + ((i < 4) ? (ty * 4 + i) : (64 + ty * 4 + (i - 4)));
    const int c0 = col0 + tx * 4;
    const int c1 = col0 + 64 + tx * 4;
    const float2 p0 = unpack2(acc2[i][0]);
    const float2 p1 = unpack2(acc2[i][1]);
    const float2 p2 = unpack2(acc2[i][2]);
    const float2 p3 = unpack2(acc2[i][3]);
    float4 o0, o1;
    o0.x = p0.x + bias[c0 + 0];
    o0.y = p0.y + bias[c0 + 1];
    o0.z = p1.x + bias[c0 + 2];
    o0.w = p1.y + bias[c0 + 3];
    o1.x = p2.x + bias[c1 + 0];
    o1.y = p2.y + bias[c1 + 1];
    o1.z = p3.x + bias[c1 + 2];
    o1.w = p3.y + bias[c1 + 3];
    *(float4*)(C + (size_t)r * HDIM + c0) = o0;
    *(float4*)(C + (size_t)r * HDIM + c1) = o1;
  }
}

// ===========================================================================
// Top-k: UNCHANGED from round 5 (validated: exact jax.lax.top_k semantics).
// ===========================================================================
#define TK_WARPS 8
#define TK_BINS 1024
#define TK_CAP 320

__global__ __launch_bounds__(256) void topk_kernel(
    const float* __restrict__ mprev, float* __restrict__ mask_out) {
  __shared__ unsigned int sh_hist[TK_WARPS][TK_BINS];
  __shared__ unsigned long long sh_cand[TK_WARPS][TK_CAP];
  __shared__ unsigned int sh_ctr[TK_WARPS][2];
  __shared__ unsigned long long sh_key[TK_WARPS][2];

  const int lane = threadIdx.x & 31;
  const int w = threadIdx.x >> 5;
  const size_t row = (size_t)blockIdx.x * TK_WARPS + w;
  float* hrow = g_h + row * HDIM;
  const float* mrow = mprev + row * HDIM;

  unsigned int* hst = sh_hist[w];
#pragma unroll
  for (int j = 0; j < TK_BINS / 32; j++) hst[j * 32 + lane] = 0;
  if (lane < 2) sh_ctr[w][lane] = 0;
  __syncwarp();

  float v[32], mp[32];
  unsigned int u[32];
  unsigned int maxbin = 0;
#pragma unroll
  for (int j = 0; j < 8; j++) {
    float4 hv = ((const float4*)hrow)[j * 32 + lane];
    float4 mv = ((const float4*)mrow)[j * 32 + lane];
    float vv[4] = {hv.x, hv.y, hv.z, hv.w};
    float mm[4] = {mv.x, mv.y, mv.z, mv.w};
#pragma unroll
    for (int i = 0; i < 4; i++) {
      float t = (mm[i] > 0.f) ? 0.f : vv[i];
      v[j * 4 + i] = t;
      mp[j * 4 + i] = mm[i];
      unsigned int uu = __float_as_uint(t * t);
      u[j * 4 + i] = uu;
      unsigned int b = uu >> 21;
      atomicAdd(&hst[b], 1u);
      maxbin = max(maxbin, b);
    }
  }
#pragma unroll
  for (int o = 16; o > 0; o >>= 1)
    maxbin = max(maxbin, __shfl_xor_sync(0xffffffffu, maxbin, o));
  __syncwarp();

  unsigned int bin0 = 0, rem0 = 0, bin1 = 0, rem1 = 0;
  bool f0 = false, f1 = false;
  unsigned int carry = 0;
  const int jstart = (int)(TK_BINS - 1 - maxbin) >> 5;
  for (int j = jstart; j < TK_BINS / 32; j++) {
    const int b = TK_BINS - 1 - (j * 32 + lane);
    const unsigned int cnt = hst[b];
    unsigned int s = cnt;
#pragma unroll
    for (int o = 1; o < 32; o <<= 1) {
      unsigned int n = __shfl_up_sync(0xffffffffu, s, o);
      if (lane >= o) s += n;
    }
    const unsigned int S = carry + s;
    const unsigned int Sp = S - cnt;
    if (cnt && S >= CDIM && Sp < CDIM)         { bin0 = b; rem0 = CDIM - Sp; f0 = true; }
    if (cnt && S >= 2 * CDIM && Sp < 2 * CDIM) { bin1 = b; rem1 = 2 * CDIM - Sp; f1 = true; }
    carry += __shfl_sync(0xffffffffu, s, 31);
    if (carry >= 2 * CDIM) break;
  }
  {
    unsigned int m0 = __ballot_sync(0xffffffffu, f0);
    int src = __ffs(m0) - 1;
    bin0 = __shfl_sync(0xffffffffu, bin0, src);
    rem0 = __shfl_sync(0xffffffffu, rem0, src);
    unsigned int m1 = __ballot_sync(0xffffffffu, f1);
    src = __ffs(m1) - 1;
    bin1 = __shfl_sync(0xffffffffu, bin1, src);
    rem1 = __shfl_sync(0xffffffffu, rem1, src);
  }
  const bool same_bin = (bin0 == bin1);

#pragma unroll
  for (int e = 0; e < 32; e++) {
    const unsigned int b = u[e] >> 21;
    const int idx = (((e >> 2) * 32 + lane) << 2) + (e & 3);
    const unsigned long long key =
        ((unsigned long long)u[e] << 10) | (unsigned long long)(1023 - idx);
    if (b == bin0) {
      unsigned int p = atomicAdd(&sh_ctr[w][0], 1u);
      if (p < TK_CAP) sh_cand[w][p] = key;
    } else if (!same_bin && b == bin1) {
      unsigned int p = atomicAdd(&sh_ctr[w][1], 1u);
      if (p < TK_CAP) sh_cand[w][TK_CAP - 1 - p] = key;
    }
  }
  __syncwarp();
  const unsigned int n0 = sh_ctr[w][0];
  const unsigned int n1 = sh_ctr[w][1];

  for (unsigned int c = lane; c < n0; c += 32) {
    const unsigned long long kc_ = sh_cand[w][c];
    unsigned int r = 0;
    for (unsigned int q = 0; q < n0; q++) r += (sh_cand[w][q] > kc_) ? 1u : 0u;
    if (r == rem0 - 1u) sh_key[w][0] = kc_;
    if (same_bin && r == rem1 - 1u) sh_key[w][1] = kc_;
  }
  if (!same_bin) {
    for (unsigned int c = lane; c < n1; c += 32) {
      const unsigned long long kc_ = sh_cand[w][TK_CAP - 1 - c];
      unsigned int r = 0;
      for (unsigned int q = 0; q < n1; q++)
        r += (sh_cand[w][TK_CAP - 1 - q] > kc_) ? 1u : 0u;
      if (r == rem1 - 1u) sh_key[w][1] = kc_;
    }
  }
  __syncwarp();
  const unsigned long long k128 = sh_key[w][0];
  const unsigned long long k256 = sh_key[w][1];

#pragma unroll
  for (int j = 0; j < 8; j++) {
    float4 ho, mo;
    float* hp = (float*)&ho;
    float* mq = (float*)&mo;
#pragma unroll
    for (int i = 0; i < 4; i++) {
      const int e = j * 4 + i;
      const int idx = (j * 32 + lane) * 4 + i;
      const unsigned long long key =
          ((unsigned long long)u[e] << 10) | (unsigned long long)(1023 - idx);
      hp[i] = (key >= k256) ? v[e] : 0.f;
      mq[i] = mp[e] + ((key >= k128) ? 1.f : 0.f);
    }
    ((float4*)hrow)[j * 32 + lane] = ho;
    ((float4*)(mask_out + row * HDIM))[j * 32 + lane] = mo;
  }
}

// ===========================================================================
// Decoder: tf32 mma.sync GEMM (legacy tensor pipe; base PTX, sm_80+).
// out[128 x 128] per CTA; 8 warps, warp tile 32x64 (2 m16 x 8 n8 mma tiles).
// K=1024 in k16 panels, double-buffered smem, one sync per panel.
// A = masked h (fp32 -> tf32 on staging), B = W[k][n] (tf32 on staging).
// Precision: tf32/fp32-acc on `out` only; contributes ~4e-5 to total rel_err.
// ===========================================================================
#define DPA 20    // A smem row stride (words): 16 used + 4 pad (bank-exact)
#define DPB 136   // B smem row stride (words): 128 used + 8 pad (bank-exact)

__device__ __forceinline__ void mma_tf32(float* d, const uint32_t* a,
                                         const uint32_t* b) {
  asm volatile(
      "mma.sync.aligned.m16n8k8.row.col.f32.tf32.tf32.f32 "
      "{%0,%1,%2,%3}, {%4,%5,%6,%7}, {%8,%9}, {%0,%1,%2,%3};"
      : "+f"(d[0]), "+f"(d[1]), "+f"(d[2]), "+f"(d[3])
      : "r"(a[0]), "r"(a[1]), "r"(a[2]), "r"(a[3]), "r"(b[0]), "r"(b[1]));
}

__global__ __launch_bounds__(256, 2) void dec_mma_kernel(
    const float* __restrict__ Wself, const float* __restrict__ bself,
    const float* __restrict__ Wsrc,  const float* __restrict__ bsrc,
    const int* __restrict__ sel, float* __restrict__ out) {
  __shared__ uint32_t As[2][128 * DPA];
  __shared__ uint32_t Bs[2][16 * DPB];

  const float* __restrict__ W;
  const float* __restrict__ bias;
  if (*sel != 0) { W = Wsrc; bias = bsrc; }
  else           { W = Wself; bias = bself; }

  const int tid = threadIdx.x;
  const int lane = tid & 31;
  const int w = tid >> 5;
  const int mi = w & 3;        // 4 m-bands of 32 rows
  const int ni = w >> 2;       // 2 n-bands of 64 cols
  const int row0 = blockIdx.y * 128;
  const int col0 = blockIdx.x * 128;
  const int g = lane >> 2;     // group id (0..7)
  const int cl = lane & 3;     // thread-in-group (0..3)

  // Staging assignments: A: thread -> (row, 8-wide k segment); B: (k-row, 8 cols)
  const int ar = tid >> 1, aseg = (tid & 1) * 8;
  const int bk = tid >> 4, bc = (tid & 15) * 8;
  const float* aptr = g_h + (size_t)(row0 + ar) * HDIM + aseg;
  const float* bptr = W + (size_t)bk * ODIM + col0 + bc;

  float acc[2][8][4];
#pragma unroll
  for (int t = 0; t < 2; t++)
#pragma unroll
    for (int j = 0; j < 8; j++)
#pragma unroll
      for (int q = 0; q < 4; q++) acc[t][j][q] = 0.f;

  // Preload panel 0.
  float4 ag0 = *(const float4*)(aptr);
  float4 ag1 = *(const float4*)(aptr + 4);
  float4 bg0 = *(const float4*)(bptr);
  float4 bg1 = *(const float4*)(bptr + 4);
  {
    uint32_t* as = &As[0][ar * DPA + aseg];
    as[0] = cvt_tf32(ag0.x); as[1] = cvt_tf32(ag0.y);
    as[2] = cvt_tf32(ag0.z); as[3] = cvt_tf32(ag0.w);
    as[4] = cvt_tf32(ag1.x); as[5] = cvt_tf32(ag1.y);
    as[6] = cvt_tf32(ag1.z); as[7] = cvt_tf32(ag1.w);
    uint32_t* bs = &Bs[0][bk * DPB + bc];
    bs[0] = cvt_tf32(bg0.x); bs[1] = cvt_tf32(bg0.y);
    bs[2] = cvt_tf32(bg0.z); bs[3] = cvt_tf32(bg0.w);
    bs[4] = cvt_tf32(bg1.x); bs[5] = cvt_tf32(bg1.y);
    bs[6] = cvt_tf32(bg1.z); bs[7] = cvt_tf32(bg1.w);
  }
  __syncthreads();

  for (int i = 0; i < HDIM / 16; i++) {
    const int buf = i & 1;
    const bool more = (i + 1 < HDIM / 16);
    if (more) {
      const float* ap = aptr + (i + 1) * 16;
      const float* bp = bptr + (size_t)(i + 1) * 16 * ODIM;
      ag0 = *(const float4*)(ap);
      ag1 = *(const float4*)(ap + 4);
      bg0 = *(const float4*)(bp);
      bg1 = *(const float4*)(bp + 4);
    }
#pragma unroll
    for (int k8 = 0; k8 < 2; k8++) {
      uint32_t af[2][4];
#pragma unroll
      for (int t = 0; t < 2; t++) {
        const int rb = (mi * 32 + t * 16 + g) * DPA + k8 * 8 + cl;
        af[t][0] = As[buf][rb];
        af[t][1] = As[buf][rb + 8 * DPA];
        af[t][2] = As[buf][rb + 4];
        af[t][3] = As[buf][rb + 8 * DPA + 4];
      }
      uint32_t bf[8][2];
#pragma unroll
      for (int j = 0; j < 8; j++) {
        const int nb = ni * 64 + j * 8 + g;
        bf[j][0] = Bs[buf][(k8 * 8 + cl) * DPB + nb];
        bf[j][1] = Bs[buf][(k8 * 8 + cl + 4) * DPB + nb];
      }
#pragma unroll
      for (int t = 0; t < 2; t++)
#pragma unroll
        for (int j = 0; j < 8; j++) mma_tf32(acc[t][j], af[t], bf[j]);
    }
    if (more) {
      const int nb = buf ^ 1;
      uint32_t* as = &As[nb][ar * DPA + aseg];
      as[0] = cvt_tf32(ag0.x); as[1] = cvt_tf32(ag0.y);
      as[2] = cvt_tf32(ag0.z); as[3] = cvt_tf32(ag0.w);
      as[4] = cvt_tf32(ag1.x); as[5] = cvt_tf32(ag1.y);
      as[6] = cvt_tf32(ag1.z); as[7] = cvt_tf32(ag1.w);
      uint32_t* bs = &Bs[nb][bk * DPB + bc];
      bs[0] = cvt_tf32(bg0.x); bs[1] = cvt_tf32(bg0.y);
      bs[2] = cvt_tf32(bg0.z); bs[3] = cvt_tf32(bg0.w);
      bs[4] = cvt_tf32(bg1.x); bs[5] = cvt_tf32(bg1.y);
      bs[6] = cvt_tf32(bg1.z); bs[7] = cvt_tf32(bg1.w);
      __syncthreads();
    }
  }

  // Epilogue: c0/c1 at (row g, cols 2cl, 2cl+1); c2/c3 at row g+8.
#pragma unroll
  for (int t = 0; t < 2; t++) {
    const int r = row0 + mi * 32 + t * 16 + g;
#pragma unroll
    for (int j = 0; j < 8; j++) {
      const int c = col0 + ni * 64 + j * 8 + cl * 2;
      const float b0v = bias[c], b1v = bias[c + 1];
      float2 o0 = make_float2(acc[t][j][0] + b0v, acc[t][j][1] + b1v);
      float2 o1 = make_float2(acc[t][j][2] + b0v, acc[t][j][3] + b1v);
      *(float2*)(out + (size_t)r * ODIM + c) = o0;
      *(float2*)(out + (size_t)(r + 8) * ODIM + c) = o1;
    }
  }
}

// ===========================================================================
// Inputs: x, mask_prev, W_enc, b_enc, W_dec_self, b_dec_self, W_dec_src,
// b_dec_src, decoder_type. Output: [out | mask_new].
// ===========================================================================
extern "C" void kernel_launch(void* const* d_in, const int* in_sizes, int n_in,
                              void* d_out, int out_size) {
  const float* x          = (const float*)d_in[0];
  const float* mask_prev  = (const float*)d_in[1];
  const float* W_enc      = (const float*)d_in[2];
  const float* b_enc      = (const float*)d_in[3];
  const float* W_dec_self = (const float*)d_in[4];
  const float* b_dec_self = (const float*)d_in[5];
  const float* W_dec_src  = (const float*)d_in[6];
  const float* b_dec_src  = (const float*)d_in[7];
  const int*   dtype      = (const int*)d_in[8];

  float* out      = (float*)d_out;
  float* mask_out = out + OUT_ELEMS;
  float* h        = nullptr;
  cudaGetSymbolAddress((void**)&h, g_h);

  dim3 g1(HDIM / 128, MROWS / 128);   // (8, 512)
  enc_kernel<<<g1, 256>>>(x, W_enc, b_enc, h);

  topk_kernel<<<MROWS / TK_WARPS, 256>>>(mask_prev, mask_out);

  dim3 g3(ODIM / 128, MROWS / 128);   // (2, 512)
  dec_mma_kernel<<<g3, 256>>>(W_dec_self, b_dec_self, W_dec_src, b_dec_src,
                              dtype, out);
}